// round 2
// baseline (speedup 1.0000x reference)
#include <cuda_runtime.h>
#include <cstdio>

#define EDIM 1024
#define HHEADS 16
#define DHEAD 64
#define RRANK 8
#define TLEN 1024
#define BBATCH 8
#define SLEN 1024

static constexpr float SCALE = 0.125f;  // D^-0.5

// ---------------- scratch (static device arrays; no allocation) -------------
__device__ float g_wq[EDIM * EDIM];            //  4 MB
__device__ float g_wkv[2 * EDIM * EDIM];       //  8 MB
__device__ float g_wo[EDIM * EDIM];            //  4 MB
__device__ float g_q[TLEN * BBATCH * EDIM];    // 32 MB  (T,B,E), already scaled
__device__ float g_kv[SLEN * BBATCH * 2 * EDIM]; // 64 MB (S,B,2E)
__device__ float g_ctx[TLEN * BBATCH * EDIM];  // 32 MB  (T,B,E)

// ---------------- kernel 1: materialize factorized weights ------------------
// wq  = in_proj_weight_q  @ tgt_factor   (E*E)
// wkv = in_proj_weight_kv @ src_factor   (2E*E)
// wo  = out_proj_weight   @ tgt_factor   (E*E)
__global__ void build_weights_kernel(const float* __restrict__ wq_f,
                                     const float* __restrict__ wkv_f,
                                     const float* __restrict__ wo_f,
                                     const float* __restrict__ tgt,
                                     const float* __restrict__ src) {
    int n = blockIdx.x * blockDim.x + threadIdx.x;
    const int NQ = EDIM * EDIM;
    const int NKV = 2 * EDIM * EDIM;
    float tf[RRANK], sf[RRANK];
#pragma unroll
    for (int r = 0; r < RRANK; r++) { tf[r] = tgt[r]; sf[r] = src[r]; }

    if (n < NQ) {
        const float* w = wq_f + (size_t)n * RRANK;
        float acc = 0.f;
#pragma unroll
        for (int r = 0; r < RRANK; r++) acc += w[r] * tf[r];
        g_wq[n] = acc;
    } else if (n < NQ + NKV) {
        int m = n - NQ;
        const float* w = wkv_f + (size_t)m * RRANK;
        float acc = 0.f;
#pragma unroll
        for (int r = 0; r < RRANK; r++) acc += w[r] * sf[r];
        g_wkv[m] = acc;
    } else if (n < NQ + NKV + NQ) {
        int m = n - NQ - NKV;
        const float* w = wo_f + (size_t)m * RRANK;
        float acc = 0.f;
#pragma unroll
        for (int r = 0; r < RRANK; r++) acc += w[r] * tf[r];
        g_wo[m] = acc;
    }
}

// ---------------- kernel 2: SGEMM  C[M,N] = alpha * A[M,K] @ B[N,K]^T -------
// Classic 128x128 tile, BK=16, 256 threads, 8x8 per-thread micro-tile.
// All problem dims divide the tile sizes; no bounds checks.
__global__ __launch_bounds__(256) void sgemm_abt_kernel(
    const float* __restrict__ A, const float* __restrict__ B,
    float* __restrict__ C, int M, int N, int K, float alpha) {
    __shared__ float As[16][128];
    __shared__ float Bs[16][128];

    const int tid = threadIdx.x;
    const int m0 = blockIdx.y * 128;
    const int n0 = blockIdx.x * 128;

    const int lrow = tid >> 2;          // 0..63
    const int lcol = (tid & 3) * 4;     // 0,4,8,12
    const int ty = tid >> 4;            // 0..15
    const int tx = tid & 15;            // 0..15

    float acc[8][8];
#pragma unroll
    for (int i = 0; i < 8; i++)
#pragma unroll
        for (int j = 0; j < 8; j++) acc[i][j] = 0.f;

    for (int k0 = 0; k0 < K; k0 += 16) {
        __syncthreads();
#pragma unroll
        for (int i = 0; i < 2; i++) {
            int row = lrow + i * 64;
            float4 av = *reinterpret_cast<const float4*>(
                A + (size_t)(m0 + row) * K + k0 + lcol);
            As[lcol + 0][row] = av.x;
            As[lcol + 1][row] = av.y;
            As[lcol + 2][row] = av.z;
            As[lcol + 3][row] = av.w;
            float4 bv = *reinterpret_cast<const float4*>(
                B + (size_t)(n0 + row) * K + k0 + lcol);
            Bs[lcol + 0][row] = bv.x;
            Bs[lcol + 1][row] = bv.y;
            Bs[lcol + 2][row] = bv.z;
            Bs[lcol + 3][row] = bv.w;
        }
        __syncthreads();
#pragma unroll
        for (int k = 0; k < 16; k++) {
            float a[8], b[8];
            const float4* ap = reinterpret_cast<const float4*>(&As[k][ty * 8]);
            const float4* bp = reinterpret_cast<const float4*>(&Bs[k][tx * 8]);
            float4 a0 = ap[0], a1 = ap[1];
            float4 b0 = bp[0], b1 = bp[1];
            a[0]=a0.x; a[1]=a0.y; a[2]=a0.z; a[3]=a0.w;
            a[4]=a1.x; a[5]=a1.y; a[6]=a1.z; a[7]=a1.w;
            b[0]=b0.x; b[1]=b0.y; b[2]=b0.z; b[3]=b0.w;
            b[4]=b1.x; b[5]=b1.y; b[6]=b1.z; b[7]=b1.w;
#pragma unroll
            for (int i = 0; i < 8; i++)
#pragma unroll
                for (int j = 0; j < 8; j++) acc[i][j] += a[i] * b[j];
        }
    }

#pragma unroll
    for (int i = 0; i < 8; i++) {
        float* crow = C + (size_t)(m0 + ty * 8 + i) * N + n0 + tx * 8;
        float4 v0 = make_float4(alpha * acc[i][0], alpha * acc[i][1],
                                alpha * acc[i][2], alpha * acc[i][3]);
        float4 v1 = make_float4(alpha * acc[i][4], alpha * acc[i][5],
                                alpha * acc[i][6], alpha * acc[i][7]);
        reinterpret_cast<float4*>(crow)[0] = v0;
        reinterpret_cast<float4*>(crow)[1] = v1;
    }
}

// ---------------- kernel 3: flash attention (fp32 SIMT) ---------------------
// grid: (T/128, B*H). block: 128 threads. One thread = one query row.
// K/V tiles of 32 keys live in shared; score reads broadcast across the block.
__global__ __launch_bounds__(128) void attn_kernel(
    const float* __restrict__ qg, const float* __restrict__ kvg,
    const unsigned char* __restrict__ mask, float* __restrict__ ctx) {
    __shared__ float4 Ks[32][16];   // 32 keys x 64 floats
    __shared__ float4 Vs[32][16];
    __shared__ float sbias[32];

    const int bh = blockIdx.y;
    const int b = bh >> 4;          // / HHEADS
    const int h = bh & 15;          // % HHEADS
    const int t = blockIdx.x * 128 + threadIdx.x;

    const float* qrow = qg + ((size_t)t * BBATCH + b) * EDIM + h * DHEAD;
    float4 qv[16];
#pragma unroll
    for (int c = 0; c < 16; c++)
        qv[c] = reinterpret_cast<const float4*>(qrow)[c];

    float4 ov[16];
#pragma unroll
    for (int c = 0; c < 16; c++) ov[c] = make_float4(0.f, 0.f, 0.f, 0.f);
    float mrow = -1e30f, lrow = 0.f;

    for (int s0 = 0; s0 < SLEN; s0 += 32) {
        __syncthreads();
#pragma unroll
        for (int i = 0; i < 4; i++) {
            int lin = threadIdx.x + i * 128;
            int row = lin >> 4;
            int col = lin & 15;
            const float* kbase =
                kvg + ((size_t)(s0 + row) * BBATCH + b) * (2 * EDIM) + h * DHEAD;
            Ks[row][col] = reinterpret_cast<const float4*>(kbase)[col];
            Vs[row][col] = reinterpret_cast<const float4*>(kbase + EDIM)[col];
        }
        if (threadIdx.x < 32)
            sbias[threadIdx.x] =
                mask[b * SLEN + s0 + threadIdx.x] ? -1e30f : 0.f;
        __syncthreads();

        float sc[32];
        float mt = mrow;
#pragma unroll
        for (int j = 0; j < 32; j++) {
            float a = 0.f;
#pragma unroll
            for (int c = 0; c < 16; c++) {
                float4 k4 = Ks[j][c];
                float4 q4 = qv[c];
                a += q4.x * k4.x;
                a += q4.y * k4.y;
                a += q4.z * k4.z;
                a += q4.w * k4.w;
            }
            a += sbias[j];
            sc[j] = a;
            mt = fmaxf(mt, a);
        }
        float corr = __expf(mrow - mt);
        lrow *= corr;
#pragma unroll
        for (int c = 0; c < 16; c++) {
            ov[c].x *= corr; ov[c].y *= corr;
            ov[c].z *= corr; ov[c].w *= corr;
        }
#pragma unroll
        for (int j = 0; j < 32; j++) {
            float p = __expf(sc[j] - mt);
            lrow += p;
#pragma unroll
            for (int c = 0; c < 16; c++) {
                float4 v4 = Vs[j][c];
                ov[c].x += p * v4.x;
                ov[c].y += p * v4.y;
                ov[c].z += p * v4.z;
                ov[c].w += p * v4.w;
            }
        }
        mrow = mt;
    }

    float inv = 1.f / lrow;
    float* crow = ctx + ((size_t)t * BBATCH + b) * EDIM + h * DHEAD;
#pragma unroll
    for (int c = 0; c < 16; c++) {
        float4 o = ov[c];
        o.x *= inv; o.y *= inv; o.z *= inv; o.w *= inv;
        reinterpret_cast<float4*>(crow)[c] = o;
    }
}

// ---------------- launch ----------------------------------------------------
extern "C" void kernel_launch(void* const* d_in, const int* in_sizes, int n_in,
                              void* d_out, int out_size) {
    const float* query = (const float*)d_in[0];          // (T,B,E)
    const float* key   = (const float*)d_in[1];          // (S,B,E)
    const float* tgt   = (const float*)d_in[2];          // (R,)
    const float* src   = (const float*)d_in[3];          // (R,)
    const float* wq_f  = (const float*)d_in[4];          // (E*E, R)
    const float* wkv_f = (const float*)d_in[5];          // (2E*E, R)
    const float* wo_f  = (const float*)d_in[6];          // (E*E, R)
    const unsigned char* mask = (const unsigned char*)d_in[7]; // (B,S) bool
    float* out = (float*)d_out;                          // (T,B,E)

    float *wq, *wkv, *wo, *q, *kv, *ctx;
    cudaGetSymbolAddress((void**)&wq, g_wq);
    cudaGetSymbolAddress((void**)&wkv, g_wkv);
    cudaGetSymbolAddress((void**)&wo, g_wo);
    cudaGetSymbolAddress((void**)&q, g_q);
    cudaGetSymbolAddress((void**)&kv, g_kv);
    cudaGetSymbolAddress((void**)&ctx, g_ctx);

    // 1. materialize weights (4M outputs)
    {
        int total = 4 * EDIM * EDIM;
        build_weights_kernel<<<(total + 255) / 256, 256>>>(wq_f, wkv_f, wo_f,
                                                           tgt, src);
    }

    const int M = TLEN * BBATCH;  // 8192

    // 2. q = query @ wq^T * SCALE    (8192 x 1024 x 1024)
    {
        dim3 grid(EDIM / 128, M / 128);
        sgemm_abt_kernel<<<grid, 256>>>(query, wq, q, M, EDIM, EDIM, SCALE);
    }

    // 3. kv = key @ wkv^T            (8192 x 2048 x 1024)
    {
        dim3 grid(2 * EDIM / 128, M / 128);
        sgemm_abt_kernel<<<grid, 256>>>(key, wkv, kv, M, 2 * EDIM, EDIM, 1.0f);
    }

    // 4. attention -> ctx (T,B,E)
    {
        dim3 grid(TLEN / 128, BBATCH * HHEADS);
        attn_kernel<<<grid, 128>>>(q, kv, mask, ctx);
    }

    // 5. out = ctx @ wo^T            (8192 x 1024 x 1024)
    {
        dim3 grid(EDIM / 128, M / 128);
        sgemm_abt_kernel<<<grid, 256>>>(ctx, wo, out, M, EDIM, EDIM, 1.0f);
    }
}

// round 4
// speedup vs baseline: 2.4133x; 2.4133x over previous
#include <cuda_runtime.h>
#include <cuda_fp16.h>
#include <cstdint>
#include <cstddef>

using u32 = uint32_t;
using u64 = uint64_t;
#define MTOT 8192

// ---------------- static scratch (no allocation) ----------------
__device__ __half g_xqh[MTOT * 1024], g_xql[MTOT * 1024];
__device__ __half g_xkh[MTOT * 1024], g_xkl[MTOT * 1024];
__device__ __half g_wqh[1024 * 1024], g_wql[1024 * 1024];
__device__ __half g_wkh[1024 * 1024], g_wkl[1024 * 1024];
__device__ __half g_wvh[1024 * 1024], g_wvl[1024 * 1024];
__device__ __half g_woh[1024 * 1024], g_wol[1024 * 1024];
__device__ __half g_qh[MTOT * 1024], g_ql[MTOT * 1024];
__device__ __half g_kh[MTOT * 1024], g_kl[MTOT * 1024];
__device__ __half g_vh[MTOT * 1024], g_vl[MTOT * 1024];
__device__ __half g_vth[MTOT * 1024], g_vtl[MTOT * 1024];
__device__ __half g_ch[MTOT * 1024], g_cl[MTOT * 1024];
__device__ float  g_sc[(size_t)128 << 20];   // 512 MB logits (bh,t,s)
__device__ __half g_pr[(size_t)128 << 20];   // 256 MB probs

// ---------------- helpers ----------------
__device__ __forceinline__ u32 smem_u32(const void* p) {
    u32 a;
    asm("{ .reg .u64 t; cvta.to.shared.u64 t, %1; cvt.u32.u64 %0, t; }"
        : "=r"(a) : "l"(p));
    return a;
}
__device__ __forceinline__ void split2(float f0, float f1, u32& h, u32& l) {
    __half a = __float2half_rn(f0), b = __float2half_rn(f1);
    h = (u32)__half_as_ushort(a) | ((u32)__half_as_ushort(b) << 16);
    __half c = __float2half_rn(f0 - __half2float(a));
    __half d = __float2half_rn(f1 - __half2float(b));
    l = (u32)__half_as_ushort(c) | ((u32)__half_as_ushort(d) << 16);
}
__device__ __forceinline__ void cpa16(u32 s, const void* g) {
    asm volatile("cp.async.cg.shared.global [%0], [%1], 16;"
                 :: "r"(s), "l"((u64)__cvta_generic_to_global(g)));
}
__device__ __forceinline__ void ldm4(u32* r, u32 addr) {
    asm volatile("ldmatrix.sync.aligned.m8n8.x4.shared.b16 {%0,%1,%2,%3}, [%4];"
                 : "=r"(r[0]), "=r"(r[1]), "=r"(r[2]), "=r"(r[3]) : "r"(addr));
}
__device__ __forceinline__ void mma16816(float* d, const u32* a, const u32* b) {
    asm volatile(
        "mma.sync.aligned.m16n8k16.row.col.f32.f16.f16.f32 "
        "{%0,%1,%2,%3},{%4,%5,%6,%7},{%8,%9},{%0,%1,%2,%3};"
        : "+f"(d[0]), "+f"(d[1]), "+f"(d[2]), "+f"(d[3])
        : "r"(a[0]), "r"(a[1]), "r"(a[2]), "r"(a[3]), "r"(b[0]), "r"(b[1]));
}

// ---------------- kernel: split fp32 inputs to hi/lo fp16 ----------------
__global__ __launch_bounds__(256) void split_inputs_k(
    const float* __restrict__ q, const float* __restrict__ kk) {
    size_t idx = (size_t)blockIdx.x * 256 + threadIdx.x;  // 0..2M-1
    size_t i = idx & ((1u << 20) - 1);
    const float* src = (idx < (1u << 20)) ? q : kk;
    __half* dh = (idx < (1u << 20)) ? g_xqh : g_xkh;
    __half* dl = (idx < (1u << 20)) ? g_xql : g_xkl;
    size_t e = i * 8;
    float4 a = ((const float4*)(src + e))[0];
    float4 b = ((const float4*)(src + e))[1];
    float f[8] = {a.x, a.y, a.z, a.w, b.x, b.y, b.z, b.w};
    u32 ph[4], pl[4];
#pragma unroll
    for (int j = 0; j < 4; j++) split2(f[2 * j], f[2 * j + 1], ph[j], pl[j]);
    *(uint4*)(dh + e) = make_uint4(ph[0], ph[1], ph[2], ph[3]);
    *(uint4*)(dl + e) = make_uint4(pl[0], pl[1], pl[2], pl[3]);
}

// ---------------- kernel: factorized weights -> split fp16 ----------------
__global__ __launch_bounds__(256) void build_weights_k(
    const float* __restrict__ wq_f, const float* __restrict__ wkv_f,
    const float* __restrict__ wo_f, const float* __restrict__ tgt,
    const float* __restrict__ src) {
    u32 n = blockIdx.x * 256 + threadIdx.x;  // 0..4M-1
    u32 seg = n >> 20, m = n & 1048575;
    const float* w;
    const float* f;
    __half *dh, *dl;
    float scale = 1.f;
    if (seg == 0) { w = wq_f + (size_t)m * 8; f = tgt; dh = g_wqh; dl = g_wql; scale = 0.125f; }
    else if (seg == 1) { w = wkv_f + (size_t)m * 8; f = src; dh = g_wkh; dl = g_wkl; }
    else if (seg == 2) { w = wkv_f + ((size_t)1048576 + m) * 8; f = src; dh = g_wvh; dl = g_wvl; }
    else { w = wo_f + (size_t)m * 8; f = tgt; dh = g_woh; dl = g_wol; }
    float acc = 0.f;
#pragma unroll
    for (int r = 0; r < 8; r++) acc += w[r] * f[r];
    acc *= scale;
    __half h = __float2half_rn(acc);
    dh[m] = h;
    dl[m] = __float2half_rn(acc - __half2float(h));
}

// ---------------- mma.sync GEMM: C = sum_t A_t[M,K] @ B_t[N,K]^T ----------
// BM=128, BK=32, 256 threads (8 warps as 4x2), double-buffered cp.async.
// EPI 0: fp32 -> CF + z*zsC (ldc=1024). EPI 1: split fp16 -> CH/CL (m,1024).
// EPI 2: split fp16 ctx scatter. ZMODE 1: per-head offsets (scores).
template <int BN, int NTERM, int ZMODE, int EPI>
__global__ __launch_bounds__(256) void gemmh(
    const __half* A0, const __half* B0, const __half* A1, const __half* B1,
    const __half* A2, const __half* B2, int K, int lda, int ldb,
    size_t zsA, size_t zsB, size_t zsC,
    float* CF, __half* CH, __half* CL) {
    constexpr int ROWS = 128 + BN;
    constexpr int STAGE = ROWS * 64;     // bytes per stage
    constexpr int NPASS = ROWS / 64;
    constexpr int NT8 = BN / 16;         // n8-tiles per warp
    extern __shared__ char smem[];
    const u32 sbase = smem_u32(smem);

    const int tid = threadIdx.x, lane = tid & 31, wid = tid >> 5;
    const int m0 = blockIdx.y * 128, n0 = blockIdx.x * BN, z = blockIdx.z;
    size_t offA, offB;
    if (ZMODE == 1) {
        size_t o = (size_t)(z >> 4) * 1024 + (size_t)(z & 15) * 64;
        offA = o; offB = o;
    } else {
        offA = (size_t)z * zsA; offB = (size_t)z * zsB;
    }
    const __half* Aarr[3] = {A0, A1, A2};
    const __half* Barr[3] = {B0, B1, B2};

    const int nkc = K >> 5;
    const int NI = NTERM * nkc;

    float acc[2][NT8][4];
#pragma unroll
    for (int a = 0; a < 2; a++)
#pragma unroll
        for (int b = 0; b < NT8; b++)
#pragma unroll
            for (int c = 0; c < 4; c++) acc[a][b][c] = 0.f;

    auto load_stage = [&](int it, int bufi) {
        const int t = it / nkc, kc = it - t * nkc;
        const __half* Ab = Aarr[t] + offA + (size_t)m0 * lda + kc * 32;
        const __half* Bb = Barr[t] + offB + (size_t)n0 * ldb + kc * 32;
        const u32 sb = sbase + bufi * STAGE;
#pragma unroll
        for (int p = 0; p < NPASS; p++) {
            const int L = p * 256 + tid;
            const int row = L >> 2, c = L & 3;
            const __half* g = (row < 128)
                ? Ab + (size_t)row * lda + c * 8
                : Bb + (size_t)(row - 128) * ldb + c * 8;
            cpa16(sb + row * 64 + ((c ^ ((row >> 1) & 3)) << 4), g);
        }
    };

    load_stage(0, 0);
    asm volatile("cp.async.commit_group;");
    int buf = 0;
    const int wm = wid >> 1, wn = wid & 1;
    for (int it = 0; it < NI; it++) {
        if (it + 1 < NI) load_stage(it + 1, buf ^ 1);
        asm volatile("cp.async.commit_group;");
        asm volatile("cp.async.wait_group 1;");
        __syncthreads();
        const u32 sb = sbase + buf * STAGE;
#pragma unroll
        for (int kstep = 0; kstep < 2; kstep++) {
            u32 ra[2][4];
#pragma unroll
            for (int mt = 0; mt < 2; mt++) {
                int row = wm * 32 + mt * 16 + (lane & 15);
                int c = kstep * 2 + (lane >> 4);
                ldm4(ra[mt], sb + row * 64 + ((c ^ ((row >> 1) & 3)) << 4));
            }
            u32 rb[NT8][2];
#pragma unroll
            for (int np = 0; np < NT8 / 2; np++) {
                int i = lane & 7, seg = lane >> 3;
                int row = 128 + wn * (BN / 2) + np * 16 + (seg >> 1) * 8 + i;
                int c = kstep * 2 + (seg & 1);
                u32 r4[4];
                ldm4(r4, sb + row * 64 + ((c ^ ((row >> 1) & 3)) << 4));
                rb[np * 2][0] = r4[0]; rb[np * 2][1] = r4[1];
                rb[np * 2 + 1][0] = r4[2]; rb[np * 2 + 1][1] = r4[3];
            }
#pragma unroll
            for (int mt = 0; mt < 2; mt++)
#pragma unroll
                for (int nt = 0; nt < NT8; nt++)
                    mma16816(acc[mt][nt], ra[mt], rb[nt]);
        }
        __syncthreads();
        buf ^= 1;
    }

    // epilogue
    const int r0 = m0 + wm * 32 + (lane >> 2);
    const int cb = n0 + wn * (BN / 2) + (lane & 3) * 2;
#pragma unroll
    for (int mt = 0; mt < 2; mt++)
#pragma unroll
        for (int nt = 0; nt < NT8; nt++) {
            int col = cb + nt * 8;
#pragma unroll
            for (int hh = 0; hh < 2; hh++) {
                int rr = r0 + mt * 16 + hh * 8;
                float f0 = acc[mt][nt][hh * 2], f1 = acc[mt][nt][hh * 2 + 1];
                if constexpr (EPI == 0) {
                    float2* d = (float2*)(CF + (size_t)z * zsC +
                                          (size_t)rr * 1024 + col);
                    *d = make_float2(f0, f1);
                } else {
                    u32 h, l;
                    split2(f0, f1, h, l);
                    size_t addr;
                    if constexpr (EPI == 1)
                        addr = (size_t)rr * 1024 + col;
                    else
                        addr = (size_t)(rr * 8 + (z >> 4)) * 1024 +
                               (size_t)(z & 15) * 64 + col;
                    *(u32*)(CH + addr) = h;
                    *(u32*)(CL + addr) = l;
                }
            }
        }
}

// ---------------- kernel: V transpose (s*8+b,1024) -> (bh*64+d, s) ----------
__global__ __launch_bounds__(256) void transpose_v_k() {
    __shared__ __half th[32][33], tl[32][33];
    int z = blockIdx.z, b = z >> 4, h = z & 15;
    int s0 = blockIdx.x * 32, d0 = blockIdx.y * 32;
    int r = threadIdx.x >> 5, c = threadIdx.x & 31;
#pragma unroll
    for (int p = 0; p < 4; p++) {
        int rr = r + p * 8;
        size_t src = (size_t)((s0 + rr) * 8 + b) * 1024 + h * 64 + d0 + c;
        th[rr][c] = g_vh[src];
        tl[rr][c] = g_vl[src];
    }
    __syncthreads();
#pragma unroll
    for (int p = 0; p < 4; p++) {
        int rr = r + p * 8;
        size_t dst = (size_t)(z * 64 + d0 + rr) * 1024 + s0 + c;
        g_vth[dst] = th[c][rr];
        g_vtl[dst] = tl[c][rr];
    }
}

// ---------------- kernel: softmax with mask, fp32 -> fp16 probs -------------
__global__ __launch_bounds__(256) void softmax_k(const unsigned char* __restrict__ mask) {
    __shared__ float warpv[8];
    __shared__ float bcast;
    const size_t row = blockIdx.x;
    const int b = (int)(row >> 14);
    const int s = threadIdx.x * 4;
    float4 v4 = *(const float4*)(g_sc + (row << 10) + s);
    float v[4] = {v4.x, v4.y, v4.z, v4.w};
    const unsigned char* mp = mask + b * 1024 + s;
#pragma unroll
    for (int j = 0; j < 4; j++)
        if (mp[j]) v[j] = -1e30f;
    float mx = fmaxf(fmaxf(v[0], v[1]), fmaxf(v[2], v[3]));
#pragma unroll
    for (int o = 16; o; o >>= 1) mx = fmaxf(mx, __shfl_xor_sync(~0u, mx, o));
    if ((threadIdx.x & 31) == 0) warpv[threadIdx.x >> 5] = mx;
    __syncthreads();
    if (threadIdx.x == 0) {
        float t = warpv[0];
#pragma unroll
        for (int i = 1; i < 8; i++) t = fmaxf(t, warpv[i]);
        bcast = t;
    }
    __syncthreads();
    mx = bcast;
    float e[4], sum = 0.f;
#pragma unroll
    for (int j = 0; j < 4; j++) { e[j] = __expf(v[j] - mx); sum += e[j]; }
#pragma unroll
    for (int o = 16; o; o >>= 1) sum += __shfl_xor_sync(~0u, sum, o);
    __syncthreads();
    if ((threadIdx.x & 31) == 0) warpv[threadIdx.x >> 5] = sum;
    __syncthreads();
    if (threadIdx.x == 0) {
        float t = 0.f;
#pragma unroll
        for (int i = 0; i < 8; i++) t += warpv[i];
        bcast = t;
    }
    __syncthreads();
    const float inv = 1.f / bcast;
    __half2* dp = (__half2*)(g_pr + (row << 10) + s);
    dp[0] = __floats2half2_rn(e[0] * inv, e[1] * inv);
    dp[1] = __floats2half2_rn(e[2] * inv, e[3] * inv);
}

// ---------------- launch ----------------
extern "C" void kernel_launch(void* const* d_in, const int* in_sizes, int n_in,
                              void* d_out, int out_size) {
    const float* query = (const float*)d_in[0];
    const float* key = (const float*)d_in[1];
    const float* tgt = (const float*)d_in[2];
    const float* src = (const float*)d_in[3];
    const float* wq_f = (const float*)d_in[4];
    const float* wkv_f = (const float*)d_in[5];
    const float* wo_f = (const float*)d_in[6];
    const unsigned char* mask = (const unsigned char*)d_in[7];
    float* out = (float*)d_out;

#define SYM(v, s) cudaGetSymbolAddress((void**)&v, s)
    __half *xqh, *xql, *xkh, *xkl, *wqh, *wql, *wkh, *wkl, *wvh, *wvl, *woh, *wol;
    __half *qh, *ql, *kh, *kl, *vh, *vl, *vth, *vtl, *ch, *cl, *pr;
    float* sc;
    SYM(xqh, g_xqh); SYM(xql, g_xql); SYM(xkh, g_xkh); SYM(xkl, g_xkl);
    SYM(wqh, g_wqh); SYM(wql, g_wql); SYM(wkh, g_wkh); SYM(wkl, g_wkl);
    SYM(wvh, g_wvh); SYM(wvl, g_wvl); SYM(woh, g_woh); SYM(wol, g_wol);
    SYM(qh, g_qh); SYM(ql, g_ql); SYM(kh, g_kh); SYM(kl, g_kl);
    SYM(vh, g_vh); SYM(vl, g_vl); SYM(vth, g_vth); SYM(vtl, g_vtl);
    SYM(ch, g_ch); SYM(cl, g_cl); SYM(pr, g_pr); SYM(sc, g_sc);

    const int SM128 = 2 * 256 * 64;  // 32 KB
    const int SM64 = 2 * 192 * 64;   // 24 KB

    split_inputs_k<<<8192, 256>>>(query, key);
    build_weights_k<<<16384, 256>>>(wq_f, wkv_f, wo_f, tgt, src);

    // q/k/v projections (3-term split, split fp16 out), M=8192, N=1024, K=1024
    gemmh<128, 3, 0, 1><<<dim3(8, 64, 1), 256, SM128>>>(
        xqh, wqh, xql, wqh, xqh, wql, 1024, 1024, 1024, 0, 0, 0, nullptr, qh, ql);
    gemmh<128, 3, 0, 1><<<dim3(8, 64, 1), 256, SM128>>>(
        xkh, wkh, xkl, wkh, xkh, wkl, 1024, 1024, 1024, 0, 0, 0, nullptr, kh, kl);
    gemmh<128, 3, 0, 1><<<dim3(8, 64, 1), 256, SM128>>>(
        xkh, wvh, xkl, wvh, xkh, wvl, 1024, 1024, 1024, 0, 0, 0, nullptr, vh, vl);

    transpose_v_k<<<dim3(32, 2, 128), 256>>>();

    // scores per head (3-term, K=64 each): q(t,:) . k(s,:), fp32 out
    gemmh<128, 3, 1, 0><<<dim3(8, 8, 128), 256, SM128>>>(
        qh, kh, ql, kh, qh, kl, 64, 8192, 8192, 0, 0, (size_t)1 << 20,
        sc, nullptr, nullptr);

    softmax_k<<<131072, 256>>>(mask);

    // ctx = P @ V^T (2-term V hi/lo), per-head, ctx split out
    gemmh<64, 2, 0, 2><<<dim3(1, 8, 128), 256, SM64>>>(
        pr, vth, pr, vtl, nullptr, nullptr, 1024, 1024, 1024,
        (size_t)1 << 20, 65536, 0, nullptr, ch, cl);

    // out = ctx @ wo^T (3-term), fp32 out
    gemmh<128, 3, 0, 0><<<dim3(8, 64, 1), 256, SM128>>>(
        ch, woh, cl, woh, ch, wol, 1024, 1024, 1024, 0, 0, 0,
        out, nullptr, nullptr);
}

// round 5
// speedup vs baseline: 3.0666x; 1.2707x over previous
#include <cuda_runtime.h>
#include <cuda_fp16.h>
#include <cstdint>
#include <cstddef>

using u32 = uint32_t;
using u64 = uint64_t;
#define MTOT 8192

// ---------------- static scratch (no allocation) ----------------
__device__ __half g_xqh[MTOT * 1024], g_xql[MTOT * 1024];
__device__ __half g_xkh[MTOT * 1024], g_xkl[MTOT * 1024];
__device__ __half g_wqh[1024 * 1024], g_wql[1024 * 1024];
__device__ __half g_wkh[1024 * 1024], g_wkl[1024 * 1024];
__device__ __half g_wvh[1024 * 1024], g_wvl[1024 * 1024];
__device__ __half g_woh[1024 * 1024], g_wol[1024 * 1024];
__device__ __half g_qh[MTOT * 1024], g_ql[MTOT * 1024];
__device__ __half g_kh[MTOT * 1024], g_kl[MTOT * 1024];
__device__ __half g_vh[MTOT * 1024], g_vl[MTOT * 1024];
__device__ __half g_vth[MTOT * 1024], g_vtl[MTOT * 1024];
__device__ __half g_ch[MTOT * 1024], g_cl[MTOT * 1024];

// ---------------- helpers ----------------
__device__ __forceinline__ u32 smem_u32(const void* p) {
    u32 a;
    asm("{ .reg .u64 t; cvta.to.shared.u64 t, %1; cvt.u32.u64 %0, t; }"
        : "=r"(a) : "l"(p));
    return a;
}
__device__ __forceinline__ void split2(float f0, float f1, u32& h, u32& l) {
    __half a = __float2half_rn(f0), b = __float2half_rn(f1);
    h = (u32)__half_as_ushort(a) | ((u32)__half_as_ushort(b) << 16);
    __half c = __float2half_rn(f0 - __half2float(a));
    __half d = __float2half_rn(f1 - __half2float(b));
    l = (u32)__half_as_ushort(c) | ((u32)__half_as_ushort(d) << 16);
}
__device__ __forceinline__ u32 pack2(float f0, float f1) {
    __half2 hh = __floats2half2_rn(f0, f1);
    return *reinterpret_cast<u32*>(&hh);
}
__device__ __forceinline__ void cpa16(u32 s, const void* g) {
    asm volatile("cp.async.cg.shared.global [%0], [%1], 16;"
                 :: "r"(s), "l"((u64)__cvta_generic_to_global(g)));
}
__device__ __forceinline__ void ldm4(u32* r, u32 addr) {
    asm volatile("ldmatrix.sync.aligned.m8n8.x4.shared.b16 {%0,%1,%2,%3}, [%4];"
                 : "=r"(r[0]), "=r"(r[1]), "=r"(r[2]), "=r"(r[3]) : "r"(addr));
}
__device__ __forceinline__ void mma16816(float* d, const u32* a, const u32* b) {
    asm volatile(
        "mma.sync.aligned.m16n8k16.row.col.f32.f16.f16.f32 "
        "{%0,%1,%2,%3},{%4,%5,%6,%7},{%8,%9},{%0,%1,%2,%3};"
        : "+f"(d[0]), "+f"(d[1]), "+f"(d[2]), "+f"(d[3])
        : "r"(a[0]), "r"(a[1]), "r"(a[2]), "r"(a[3]), "r"(b[0]), "r"(b[1]));
}

// ---------------- kernel: split fp32 inputs to hi/lo fp16 ----------------
__global__ __launch_bounds__(256) void split_inputs_k(
    const float* __restrict__ q, const float* __restrict__ kk) {
    size_t idx = (size_t)blockIdx.x * 256 + threadIdx.x;  // 0..2M-1
    size_t i = idx & ((1u << 20) - 1);
    const float* src = (idx < (1u << 20)) ? q : kk;
    __half* dh = (idx < (1u << 20)) ? g_xqh : g_xkh;
    __half* dl = (idx < (1u << 20)) ? g_xql : g_xkl;
    size_t e = i * 8;
    float4 a = ((const float4*)(src + e))[0];
    float4 b = ((const float4*)(src + e))[1];
    float f[8] = {a.x, a.y, a.z, a.w, b.x, b.y, b.z, b.w};
    u32 ph[4], pl[4];
#pragma unroll
    for (int j = 0; j < 4; j++) split2(f[2 * j], f[2 * j + 1], ph[j], pl[j]);
    *(uint4*)(dh + e) = make_uint4(ph[0], ph[1], ph[2], ph[3]);
    *(uint4*)(dl + e) = make_uint4(pl[0], pl[1], pl[2], pl[3]);
}

// ---------------- kernel: factorized weights -> split fp16 ----------------
__global__ __launch_bounds__(256) void build_weights_k(
    const float* __restrict__ wq_f, const float* __restrict__ wkv_f,
    const float* __restrict__ wo_f, const float* __restrict__ tgt,
    const float* __restrict__ src) {
    u32 n = blockIdx.x * 256 + threadIdx.x;  // 0..4M-1
    u32 seg = n >> 20, m = n & 1048575;
    const float* w;
    const float* f;
    __half *dh, *dl;
    float scale = 1.f;
    if (seg == 0) { w = wq_f + (size_t)m * 8; f = tgt; dh = g_wqh; dl = g_wql; scale = 0.125f; }
    else if (seg == 1) { w = wkv_f + (size_t)m * 8; f = src; dh = g_wkh; dl = g_wkl; }
    else if (seg == 2) { w = wkv_f + ((size_t)1048576 + m) * 8; f = src; dh = g_wvh; dl = g_wvl; }
    else { w = wo_f + (size_t)m * 8; f = tgt; dh = g_woh; dl = g_wol; }
    float acc = 0.f;
#pragma unroll
    for (int r = 0; r < 8; r++) acc += w[r] * f[r];
    acc *= scale;
    __half h = __float2half_rn(acc);
    dh[m] = h;
    dl[m] = __float2half_rn(acc - __half2float(h));
}

// ---------------- mma.sync GEMM: C = sum_t A_t[M,K] @ B_t[N,K]^T ----------
// BM=128, BN=128, BK=32, 256 threads (8 warps as 4x2), double-buffered.
// EPI 0: fp32 -> CF (ld 1024). EPI 1: split fp16 -> CH/CL (m,1024).
template <int BN, int NTERM, int EPI>
__global__ __launch_bounds__(256) void gemmh(
    const __half* A0, const __half* B0, const __half* A1, const __half* B1,
    const __half* A2, const __half* B2, int K, int lda, int ldb,
    float* CF, __half* CH, __half* CL) {
    constexpr int ROWS = 128 + BN;
    constexpr int STAGE = ROWS * 64;
    constexpr int NPASS = ROWS / 64;
    constexpr int NT8 = BN / 16;
    extern __shared__ char smem[];
    const u32 sbase = smem_u32(smem);

    const int tid = threadIdx.x, lane = tid & 31, wid = tid >> 5;
    const int m0 = blockIdx.y * 128, n0 = blockIdx.x * BN;
    const __half* Aarr[3] = {A0, A1, A2};
    const __half* Barr[3] = {B0, B1, B2};

    const int nkc = K >> 5;
    const int NI = NTERM * nkc;

    float acc[2][NT8][4];
#pragma unroll
    for (int a = 0; a < 2; a++)
#pragma unroll
        for (int b = 0; b < NT8; b++)
#pragma unroll
            for (int c = 0; c < 4; c++) acc[a][b][c] = 0.f;

    auto load_stage = [&](int it, int bufi) {
        const int t = it / nkc, kc = it - t * nkc;
        const __half* Ab = Aarr[t] + (size_t)m0 * lda + kc * 32;
        const __half* Bb = Barr[t] + (size_t)n0 * ldb + kc * 32;
        const u32 sb = sbase + bufi * STAGE;
#pragma unroll
        for (int p = 0; p < NPASS; p++) {
            const int L = p * 256 + tid;
            const int row = L >> 2, c = L & 3;
            const __half* g = (row < 128)
                ? Ab + (size_t)row * lda + c * 8
                : Bb + (size_t)(row - 128) * ldb + c * 8;
            cpa16(sb + row * 64 + ((c ^ ((row >> 1) & 3)) << 4), g);
        }
    };

    load_stage(0, 0);
    asm volatile("cp.async.commit_group;");
    int buf = 0;
    const int wm = wid >> 1, wn = wid & 1;
    for (int it = 0; it < NI; it++) {
        if (it + 1 < NI) load_stage(it + 1, buf ^ 1);
        asm volatile("cp.async.commit_group;");
        asm volatile("cp.async.wait_group 1;");
        __syncthreads();
        const u32 sb = sbase + buf * STAGE;
#pragma unroll
        for (int kstep = 0; kstep < 2; kstep++) {
            u32 ra[2][4];
#pragma unroll
            for (int mt = 0; mt < 2; mt++) {
                int row = wm * 32 + mt * 16 + (lane & 15);
                int c = kstep * 2 + (lane >> 4);
                ldm4(ra[mt], sb + row * 64 + ((c ^ ((row >> 1) & 3)) << 4));
            }
            u32 rb[NT8][2];
#pragma unroll
            for (int np = 0; np < NT8 / 2; np++) {
                int i = lane & 7, seg = lane >> 3;
                int row = 128 + wn * (BN / 2) + np * 16 + (seg >> 1) * 8 + i;
                int c = kstep * 2 + (seg & 1);
                u32 r4[4];
                ldm4(r4, sb + row * 64 + ((c ^ ((row >> 1) & 3)) << 4));
                rb[np * 2][0] = r4[0]; rb[np * 2][1] = r4[1];
                rb[np * 2 + 1][0] = r4[2]; rb[np * 2 + 1][1] = r4[3];
            }
#pragma unroll
            for (int mt = 0; mt < 2; mt++)
#pragma unroll
                for (int nt = 0; nt < NT8; nt++)
                    mma16816(acc[mt][nt], ra[mt], rb[nt]);
        }
        __syncthreads();
        buf ^= 1;
    }

    const int r0 = m0 + wm * 32 + (lane >> 2);
    const int cb = n0 + wn * (BN / 2) + (lane & 3) * 2;
#pragma unroll
    for (int mt = 0; mt < 2; mt++)
#pragma unroll
        for (int nt = 0; nt < NT8; nt++) {
            int col = cb + nt * 8;
#pragma unroll
            for (int hh = 0; hh < 2; hh++) {
                int rr = r0 + mt * 16 + hh * 8;
                float f0 = acc[mt][nt][hh * 2], f1 = acc[mt][nt][hh * 2 + 1];
                if constexpr (EPI == 0) {
                    float2* d = (float2*)(CF + (size_t)rr * 1024 + col);
                    *d = make_float2(f0, f1);
                } else {
                    u32 h, l;
                    split2(f0, f1, h, l);
                    size_t addr = (size_t)rr * 1024 + col;
                    *(u32*)(CH + addr) = h;
                    *(u32*)(CL + addr) = l;
                }
            }
        }
}

// ---------------- kernel: V transpose (s*8+b,1024) -> (bh*64+d, s) ----------
__global__ __launch_bounds__(256) void transpose_v_k() {
    __shared__ __half th[32][33], tl[32][33];
    int z = blockIdx.z, b = z >> 4, h = z & 15;
    int s0 = blockIdx.x * 32, d0 = blockIdx.y * 32;
    int r = threadIdx.x >> 5, c = threadIdx.x & 31;
#pragma unroll
    for (int p = 0; p < 4; p++) {
        int rr = r + p * 8;
        size_t src = (size_t)((s0 + rr) * 8 + b) * 1024 + h * 64 + d0 + c;
        th[rr][c] = g_vh[src];
        tl[rr][c] = g_vl[src];
    }
    __syncthreads();
#pragma unroll
    for (int p = 0; p < 4; p++) {
        int rr = r + p * 8;
        size_t dst = (size_t)(z * 64 + d0 + rr) * 1024 + s0 + c;
        g_vth[dst] = th[c][rr];
        g_vtl[dst] = tl[c][rr];
    }
}

// ---------------- fused flash attention ----------------
// grid (T/128, B*H). 256 threads = 8 warps; warp owns 16 q rows.
// s-tiles of 64 keys, double-buffered: kh,kl,vth,vtl tiles (64x64 each).
// 3-term split S (qh.kh + ql.kh + qh.kl), online softmax, ctx += P.Vh + P.Vl.
__global__ __launch_bounds__(256) void attn_fused_k(const unsigned char* __restrict__ mask) {
    extern __shared__ char smem[];
    const u32 sbase = smem_u32(smem);
    const int tid = threadIdx.x, lane = tid & 31, w = tid >> 5;
    const int z = blockIdx.y, b = z >> 4, h = z & 15;
    const int t0 = blockIdx.x * 128;
    const int r = lane >> 2, cp = (lane & 3) * 2;

    // Q fragments: A-frag layout a0=(r,c) a1=(r+8,c) a2=(r,c+8) a3=(r+8,c+8)
    u32 qa[2][4][4];
    {
        const int mrow = t0 + w * 16 + r;
#pragma unroll
        for (int c = 0; c < 4; c++)
#pragma unroll
            for (int i = 0; i < 4; i++) {
                int mm = mrow + (i & 1) * 8;
                int col = h * 64 + c * 16 + cp + (i >> 1) * 8;
                size_t ad = ((size_t)(mm * 8 + b)) * 1024 + col;
                qa[0][c][i] = *(const u32*)(g_qh + ad);
                qa[1][c][i] = *(const u32*)(g_ql + ad);
            }
    }

    float ctx[8][4];
#pragma unroll
    for (int j = 0; j < 8; j++)
#pragma unroll
        for (int c = 0; c < 4; c++) ctx[j][c] = 0.f;
    float m0 = -1e30f, m1 = -1e30f, l0 = 0.f, l1 = 0.f;

    auto load_stage = [&](int it) {
        const int st = it & 1;
        const int s0 = it * 64;
        const u32 sb = sbase + st * 32768;
#pragma unroll
        for (int p = 0; p < 8; p++) {
            int L = p * 256 + tid;
            int tile = L >> 9, rr = (L >> 3) & 63, c = L & 7;
            const __half* g;
            if (tile == 0)
                g = g_kh + ((size_t)((s0 + rr) * 8 + b)) * 1024 + h * 64 + c * 8;
            else if (tile == 1)
                g = g_kl + ((size_t)((s0 + rr) * 8 + b)) * 1024 + h * 64 + c * 8;
            else if (tile == 2)
                g = g_vth + ((size_t)(z * 64 + rr)) * 1024 + s0 + c * 8;
            else
                g = g_vtl + ((size_t)(z * 64 + rr)) * 1024 + s0 + c * 8;
            cpa16(sb + tile * 8192 + rr * 128 + ((c ^ (rr & 7)) << 4), g);
        }
        if (tid < 64)
            ((float*)(smem + 65536 + st * 256))[tid] =
                mask[b * 1024 + s0 + tid] ? -1e30f : 0.f;
    };

    load_stage(0);
    asm volatile("cp.async.commit_group;");
    int buf = 0;
    for (int it = 0; it < 16; it++) {
        if (it < 15) load_stage(it + 1);
        asm volatile("cp.async.commit_group;");
        asm volatile("cp.async.wait_group 1;");
        __syncthreads();
        const u32 sb = sbase + buf * 32768;

        float sc[8][4];
#pragma unroll
        for (int j = 0; j < 8; j++)
#pragma unroll
            for (int c = 0; c < 4; c++) sc[j][c] = 0.f;

        // S = qh.kh + ql.kh + qh.kl
        const int i8 = lane & 7, seg = lane >> 3;
#pragma unroll
        for (int c = 0; c < 4; c++) {
            u32 bf[8][2];
#pragma unroll
            for (int np = 0; np < 4; np++) {
                int row = np * 16 + (seg >> 1) * 8 + i8;
                int cc = c * 2 + (seg & 1);
                u32 r4[4];
                ldm4(r4, sb + row * 128 + ((cc ^ (row & 7)) << 4));
                bf[np * 2][0] = r4[0]; bf[np * 2][1] = r4[1];
                bf[np * 2 + 1][0] = r4[2]; bf[np * 2 + 1][1] = r4[3];
            }
#pragma unroll
            for (int j = 0; j < 8; j++) mma16816(sc[j], qa[0][c], bf[j]);
#pragma unroll
            for (int j = 0; j < 8; j++) mma16816(sc[j], qa[1][c], bf[j]);
        }
#pragma unroll
        for (int c = 0; c < 4; c++) {
            u32 bf[8][2];
#pragma unroll
            for (int np = 0; np < 4; np++) {
                int row = np * 16 + (seg >> 1) * 8 + i8;
                int cc = c * 2 + (seg & 1);
                u32 r4[4];
                ldm4(r4, sb + 8192 + row * 128 + ((cc ^ (row & 7)) << 4));
                bf[np * 2][0] = r4[0]; bf[np * 2][1] = r4[1];
                bf[np * 2 + 1][0] = r4[2]; bf[np * 2 + 1][1] = r4[3];
            }
#pragma unroll
            for (int j = 0; j < 8; j++) mma16816(sc[j], qa[0][c], bf[j]);
        }

        // mask bias + online softmax
        const float* bias = (const float*)(smem + 65536 + buf * 256);
        float mx0 = -1e30f, mx1 = -1e30f;
#pragma unroll
        for (int j = 0; j < 8; j++) {
            int col = j * 8 + cp;
            float b0 = bias[col], b1 = bias[col + 1];
            sc[j][0] += b0; sc[j][1] += b1;
            sc[j][2] += b0; sc[j][3] += b1;
            mx0 = fmaxf(mx0, fmaxf(sc[j][0], sc[j][1]));
            mx1 = fmaxf(mx1, fmaxf(sc[j][2], sc[j][3]));
        }
        mx0 = fmaxf(mx0, __shfl_xor_sync(~0u, mx0, 1));
        mx0 = fmaxf(mx0, __shfl_xor_sync(~0u, mx0, 2));
        mx1 = fmaxf(mx1, __shfl_xor_sync(~0u, mx1, 1));
        mx1 = fmaxf(mx1, __shfl_xor_sync(~0u, mx1, 2));
        float nm0 = fmaxf(m0, mx0), nm1 = fmaxf(m1, mx1);
        float cr0 = __expf(m0 - nm0), cr1 = __expf(m1 - nm1);
        m0 = nm0; m1 = nm1;
        float sum0 = 0.f, sum1 = 0.f;
#pragma unroll
        for (int j = 0; j < 8; j++) {
            sc[j][0] = __expf(sc[j][0] - nm0);
            sc[j][1] = __expf(sc[j][1] - nm0);
            sc[j][2] = __expf(sc[j][2] - nm1);
            sc[j][3] = __expf(sc[j][3] - nm1);
            sum0 += sc[j][0] + sc[j][1];
            sum1 += sc[j][2] + sc[j][3];
        }
        sum0 += __shfl_xor_sync(~0u, sum0, 1);
        sum0 += __shfl_xor_sync(~0u, sum0, 2);
        sum1 += __shfl_xor_sync(~0u, sum1, 1);
        sum1 += __shfl_xor_sync(~0u, sum1, 2);
        l0 = l0 * cr0 + sum0;
        l1 = l1 * cr1 + sum1;
#pragma unroll
        for (int j = 0; j < 8; j++) {
            ctx[j][0] *= cr0; ctx[j][1] *= cr0;
            ctx[j][2] *= cr1; ctx[j][3] *= cr1;
        }

        // P fragments (C-frag -> A-frag identity)
        u32 pa[4][4];
#pragma unroll
        for (int c = 0; c < 4; c++) {
            pa[c][0] = pack2(sc[2 * c][0], sc[2 * c][1]);
            pa[c][1] = pack2(sc[2 * c][2], sc[2 * c][3]);
            pa[c][2] = pack2(sc[2 * c + 1][0], sc[2 * c + 1][1]);
            pa[c][3] = pack2(sc[2 * c + 1][2], sc[2 * c + 1][3]);
        }

        // ctx += P @ Vh^T + P @ Vl^T  (vt tiles: rows=d, cols=s)
#pragma unroll
        for (int c = 0; c < 4; c++) {
            u32 bv[8][2];
#pragma unroll
            for (int np = 0; np < 4; np++) {
                int row = np * 16 + (seg >> 1) * 8 + i8;
                int cc = c * 2 + (seg & 1);
                u32 r4[4];
                ldm4(r4, sb + 16384 + row * 128 + ((cc ^ (row & 7)) << 4));
                bv[np * 2][0] = r4[0]; bv[np * 2][1] = r4[1];
                bv[np * 2 + 1][0] = r4[2]; bv[np * 2 + 1][1] = r4[3];
            }
#pragma unroll
            for (int j = 0; j < 8; j++) mma16816(ctx[j], pa[c], bv[j]);
#pragma unroll
            for (int np = 0; np < 4; np++) {
                int row = np * 16 + (seg >> 1) * 8 + i8;
                int cc = c * 2 + (seg & 1);
                u32 r4[4];
                ldm4(r4, sb + 24576 + row * 128 + ((cc ^ (row & 7)) << 4));
                bv[np * 2][0] = r4[0]; bv[np * 2][1] = r4[1];
                bv[np * 2 + 1][0] = r4[2]; bv[np * 2 + 1][1] = r4[3];
            }
#pragma unroll
            for (int j = 0; j < 8; j++) mma16816(ctx[j], pa[c], bv[j]);
        }
        __syncthreads();
        buf ^= 1;
    }

    // epilogue: normalize, split fp16, store to per-head ctx layout
    const float inv0 = 1.f / l0, inv1 = 1.f / l1;
    const int mrow = t0 + w * 16 + r;
#pragma unroll
    for (int j = 0; j < 8; j++) {
        int col = h * 64 + j * 8 + cp;
        u32 hh, ll;
        split2(ctx[j][0] * inv0, ctx[j][1] * inv0, hh, ll);
        size_t a0 = ((size_t)(mrow * 8 + b)) * 1024 + col;
        *(u32*)(g_ch + a0) = hh;
        *(u32*)(g_cl + a0) = ll;
        split2(ctx[j][2] * inv1, ctx[j][3] * inv1, hh, ll);
        size_t a1 = ((size_t)((mrow + 8) * 8 + b)) * 1024 + col;
        *(u32*)(g_ch + a1) = hh;
        *(u32*)(g_cl + a1) = ll;
    }
}

// ---------------- launch ----------------
extern "C" void kernel_launch(void* const* d_in, const int* in_sizes, int n_in,
                              void* d_out, int out_size) {
    const float* query = (const float*)d_in[0];
    const float* key = (const float*)d_in[1];
    const float* tgt = (const float*)d_in[2];
    const float* src = (const float*)d_in[3];
    const float* wq_f = (const float*)d_in[4];
    const float* wkv_f = (const float*)d_in[5];
    const float* wo_f = (const float*)d_in[6];
    const unsigned char* mask = (const unsigned char*)d_in[7];
    float* out = (float*)d_out;

#define SYM(v, s) cudaGetSymbolAddress((void**)&v, s)
    __half *xqh, *xql, *xkh, *xkl, *wqh, *wql, *wkh, *wkl, *wvh, *wvl, *woh, *wol;
    __half *qh, *ql, *kh, *kl, *vh, *vl, *ch, *cl;
    SYM(xqh, g_xqh); SYM(xql, g_xql); SYM(xkh, g_xkh); SYM(xkl, g_xkl);
    SYM(wqh, g_wqh); SYM(wql, g_wql); SYM(wkh, g_wkh); SYM(wkl, g_wkl);
    SYM(wvh, g_wvh); SYM(wvl, g_wvl); SYM(woh, g_woh); SYM(wol, g_wol);
    SYM(qh, g_qh); SYM(ql, g_ql); SYM(kh, g_kh); SYM(kl, g_kl);
    SYM(vh, g_vh); SYM(vl, g_vl); SYM(ch, g_ch); SYM(cl, g_cl);

    const int SM128 = 2 * 256 * 64;   // 32 KB for gemmh
    const int SMATT = 2 * 32768 + 512; // 66 KB for fused attention
    cudaFuncSetAttribute(attn_fused_k,
                         cudaFuncAttributeMaxDynamicSharedMemorySize, SMATT);

    split_inputs_k<<<8192, 256>>>(query, key);
    build_weights_k<<<16384, 256>>>(wq_f, wkv_f, wo_f, tgt, src);

    // q/k/v projections (3-term split, split fp16 out), M=8192, N=1024, K=1024
    gemmh<128, 3, 1><<<dim3(8, 64), 256, SM128>>>(
        xqh, wqh, xql, wqh, xqh, wql, 1024, 1024, 1024, nullptr, qh, ql);
    gemmh<128, 3, 1><<<dim3(8, 64), 256, SM128>>>(
        xkh, wkh, xkl, wkh, xkh, wkl, 1024, 1024, 1024, nullptr, kh, kl);
    gemmh<128, 3, 1><<<dim3(8, 64), 256, SM128>>>(
        xkh, wvh, xkl, wvh, xkh, wvl, 1024, 1024, 1024, nullptr, vh, vl);

    transpose_v_k<<<dim3(32, 2, 128), 256>>>();

    // fused attention: scores + mask + softmax + P@V
    attn_fused_k<<<dim3(8, 128), 256, SMATT>>>(mask);

    // out = ctx @ wo^T (3-term), fp32 out
    gemmh<128, 3, 0><<<dim3(8, 64), 256, SM128>>>(
        ch, woh, cl, woh, ch, wol, 1024, 1024, 1024, out, nullptr, nullptr);
}